// round 14
// baseline (speedup 1.0000x reference)
#include <cuda_runtime.h>

#define NB        10000
#define VOCAB     10000
#define SEQ       80
#define EMB       100
#define UNITS     64
#define RPB       9           // rows per block -> grid = 1112 (single wave @ occ 8)
#define GRID      ((NB + RPB - 1) / RPB)   // 1112
#define NTHREADS  64          // 2 warps; warp w owns k-half [w*32, w*32+32)
#define KP        16          // k-pairs per warp
#define RRED      5           // reduce rows: warp0 -> 0..4, warp1 -> 4..8 (overlap benign)

// precomputed ETable[v][u] = emb[v] @ Wx[:,u] + b[u]
__device__ float g_etable[VOCAB * UNITS];

typedef unsigned long long u64;

__device__ __forceinline__ void fma2(u64& d, u64 a, u64 b) {
    asm("fma.rn.f32x2 %0, %1, %2, %0;" : "+l"(d) : "l"(a), "l"(b));
}
__device__ __forceinline__ u64 mul2(u64 a, u64 b) {
    u64 r; asm("mul.rn.f32x2 %0, %1, %2;" : "=l"(r) : "l"(a), "l"(b)); return r;
}
__device__ __forceinline__ u64 packf2(float lo, float hi) {
    u64 r; asm("mov.b64 %0, {%1, %2};" : "=l"(r) : "f"(lo), "f"(hi)); return r;
}
__device__ __forceinline__ float foldf(u64 v) {
    float lo, hi;
    asm("mov.b64 {%0, %1}, %2;" : "=f"(lo), "=f"(hi) : "l"(v));
    return lo + hi;
}
__device__ __forceinline__ float tanhx(float x) {
    float r; asm("tanh.approx.f32 %0, %1;" : "=f"(r) : "f"(x)); return r;
}

// ============ kernel 1: ETable = emb @ Wx + b (one-shot, 64M MACs) ============
__global__ __launch_bounds__(256)
void build_etable(const float* __restrict__ emb,
                  const float* __restrict__ Wx,
                  const float* __restrict__ bias)
{
    const int w = threadIdx.x >> 5, l = threadIdx.x & 31;
    const int row = blockIdx.x * 8 + w;      // 1250 * 8 = 10000 exact
    const int u = l * 2;
    float2 acc = make_float2(bias[u], bias[u + 1]);
    const float* er = emb + row * EMB;
    #pragma unroll 4
    for (int e = 0; e < EMB; ++e) {
        float xe = __ldg(er + e);
        float2 wv = *(const float2*)(Wx + e * UNITS + u);
        acc.x = fmaf(xe, wv.x, acc.x);
        acc.y = fmaf(xe, wv.y, acc.y);
    }
    *(float2*)(g_etable + row * UNITS + u) = acc;
}

// ===== kernel 2: 2-warp k-split, slim exchange (publish partner rows only) =====
__global__ __launch_bounds__(NTHREADS, 8)
void rnn_scan(const int* __restrict__ tokens,
              const float* __restrict__ Wh,
              const float* __restrict__ Wfc,
              const float* __restrict__ bfc,
              float* __restrict__ out)
{
    __shared__ float  h_s[RPB][UNITS];          // 2304 B
    __shared__ float2 part_s[2][RPB][32];       // 4608 B: [writer warp][row][lane]
    __shared__ int    tok_s[SEQ][RPB];          // 2880 B (pre-scaled offsets)

    const int tid  = threadIdx.x;
    const int w    = tid >> 5;                  // warp: k-half owner
    const int l    = tid & 31;
    const int u0   = 2 * l;                     // units owned: u0, u0+1
    const int row0 = blockIdx.x * RPB;

    // ---- stage tokens (transposed [t][r]), clamped + pre-scaled ----
    for (int i = tid; i < SEQ * RPB; i += NTHREADS) {
        int t = i / RPB, r = i - t * RPB;
        int gr = row0 + r;
        if (gr >= NB) gr = NB - 1;              // clamp ragged tail
        tok_s[t][r] = tokens[gr * SEQ + t] * UNITS;
    }
    // ---- zero h ----
    for (int i = tid; i < RPB * UNITS; i += NTHREADS)
        ((float*)h_s)[i] = 0.0f;

    // ---- this warp's k-half of Wh, k-paired, into 32 u64 registers ----
    u64 wu0[KP], wu1[KP];
    #pragma unroll
    for (int k2 = 0; k2 < KP; ++k2) {
        int kp = w * KP + k2;
        float2 a = *(const float2*)(Wh + (2 * kp)     * UNITS + u0);
        float2 b = *(const float2*)(Wh + (2 * kp + 1) * UNITS + u0);
        wu0[k2] = packf2(a.x, b.x);
        wu1[k2] = packf2(a.y, b.y);
    }
    __syncthreads();

    // own reduce rows: w0 -> 0..4, w1 -> 4..8 (row 4 duplicated, benign)
    // partner's reduce rows (to publish): w0 -> 4..8, w1 -> 0..4
    const int rown = w * 4;                     // base of own reduce set
    const int rpub = (1 - w) * 4;               // base of partner's reduce set

    // ---- xp(0) for own reduce rows ----
    float2 xc[RRED];
    #pragma unroll
    for (int i = 0; i < RRED; ++i)
        xc[i] = *(const float2*)(g_etable + tok_s[0][rown + i] + u0);

    for (int t = 0; t < SEQ; ++t) {
        // ---- partial h @ Wh over this warp's k-half ----
        u64 a0[RPB], a1[RPB];
        #pragma unroll
        for (int r = 0; r < RPB; ++r) {             // j = 0: init via MUL2
            ulonglong2 hv = *(const ulonglong2*)(&h_s[r][w * 32]);   // broadcast
            a0[r] = mul2(hv.x, wu0[0]);
            a1[r] = mul2(hv.x, wu1[0]);
            fma2(a0[r], hv.y, wu0[1]);
            fma2(a1[r], hv.y, wu1[1]);
        }
        #pragma unroll
        for (int j = 1; j < 8; ++j) {               // remaining 7 j-groups
            #pragma unroll
            for (int r = 0; r < RPB; ++r) {
                ulonglong2 hv = *(const ulonglong2*)(&h_s[r][w * 32 + 4 * j]);
                fma2(a0[r], hv.x, wu0[2 * j]);
                fma2(a1[r], hv.x, wu1[2 * j]);
                fma2(a0[r], hv.y, wu0[2 * j + 1]);
                fma2(a1[r], hv.y, wu1[2 * j + 1]);
            }
        }

        // ---- publish ONLY partner's 5 reduce rows (fold on the fly) ----
        #pragma unroll
        for (int i = 0; i < RRED; ++i) {
            int r = rpub + i;
            part_s[w][r][l] = make_float2(foldf(a0[r]), foldf(a1[r]));
        }
        // ---- own reduce rows: partial stays in registers ----
        float2 fp[RRED];
        #pragma unroll
        for (int i = 0; i < RRED; ++i) {
            int r = rown + i;
            fp[i] = make_float2(foldf(a0[r]), foldf(a1[r]));
        }
        __syncthreads();    // partner partials visible; all h reads done

        // ---- reduce + tanh + write new h for own rows ----
        #pragma unroll
        for (int i = 0; i < RRED; ++i) {
            int r = rown + i;
            float2 po = part_s[1 - w][r][l];
            float v0 = fp[i].x + po.x + xc[i].x;
            float v1 = fp[i].y + po.y + xc[i].y;
            *(u64*)(&h_s[r][u0]) = packf2(tanhx(v0), tanhx(v1));
        }

        // ---- reload xc for t+1 (covered by barrier + next compute phase) ----
        const int tn = (t + 1 < SEQ) ? (t + 1) : (SEQ - 1);
        #pragma unroll
        for (int i = 0; i < RRED; ++i)
            xc[i] = *(const float2*)(g_etable + tok_s[tn][rown + i] + u0);

        __syncthreads();    // new h visible to both warps
    }

    // ---- final FC + sigmoid: threads 0..8 each handle one row ----
    if (tid < RPB && row0 + tid < NB) {
        const float* hf = h_s[tid];
        float dot = 0.0f;
        #pragma unroll 8
        for (int v = 0; v < UNITS; ++v) dot += hf[v] * __ldg(Wfc + v);
        float logit = dot + __ldg(bfc);
        out[row0 + tid] = 1.0f / (1.0f + __expf(-logit));
    }
}

extern "C" void kernel_launch(void* const* d_in, const int* in_sizes, int n_in,
                              void* d_out, int out_size) {
    const int*   tokens = (const int*)  d_in[0];
    const float* emb    = (const float*)d_in[1];
    const float* Wx     = (const float*)d_in[2];
    const float* Wh     = (const float*)d_in[3];
    const float* b      = (const float*)d_in[4];
    const float* Wfc    = (const float*)d_in[5];
    const float* bfc    = (const float*)d_in[6];
    float* out          = (float*)d_out;

    build_etable<<<VOCAB / 8, 256>>>(emb, Wx, b);
    rnn_scan<<<GRID, NTHREADS>>>(tokens, Wh, Wfc, bfc, out);
}

// round 15
// speedup vs baseline: 1.0647x; 1.0647x over previous
#include <cuda_runtime.h>

#define NB        10000
#define VOCAB     10000
#define SEQ       80
#define EMB       100
#define UNITS     64
#define RPB       9           // rows per block -> grid = 1112 (single wave @ occ 8)
#define GRID      ((NB + RPB - 1) / RPB)   // 1112
#define NTHREADS  64          // 2 warps; warp w owns k-half [w*32, w*32+32)
#define KP        16          // k-pairs per warp

// precomputed ETable[v][u] = emb[v] @ Wx[:,u] + b[u]
__device__ float g_etable[VOCAB * UNITS];

typedef unsigned long long u64;

__device__ __forceinline__ void fma2(u64& d, u64 a, u64 b) {
    asm("fma.rn.f32x2 %0, %1, %2, %0;" : "+l"(d) : "l"(a), "l"(b));
}
__device__ __forceinline__ u64 mul2(u64 a, u64 b) {
    u64 r; asm("mul.rn.f32x2 %0, %1, %2;" : "=l"(r) : "l"(a), "l"(b)); return r;
}
__device__ __forceinline__ u64 packf2(float lo, float hi) {
    u64 r; asm("mov.b64 %0, {%1, %2};" : "=l"(r) : "f"(lo), "f"(hi)); return r;
}
__device__ __forceinline__ float foldf(u64 v) {
    float lo, hi;
    asm("mov.b64 {%0, %1}, %2;" : "=f"(lo), "=f"(hi) : "l"(v));
    return lo + hi;
}
__device__ __forceinline__ float tanhx(float x) {
    float r; asm("tanh.approx.f32 %0, %1;" : "=f"(r) : "f"(x)); return r;
}

// ============ kernel 1: ETable = emb @ Wx + b (one-shot, 64M MACs) ============
__global__ __launch_bounds__(256)
void build_etable(const float* __restrict__ emb,
                  const float* __restrict__ Wx,
                  const float* __restrict__ bias)
{
    const int w = threadIdx.x >> 5, l = threadIdx.x & 31;
    const int row = blockIdx.x * 8 + w;      // 1250 * 8 = 10000 exact
    const int u = l * 2;
    float2 acc = make_float2(bias[u], bias[u + 1]);
    const float* er = emb + row * EMB;
    #pragma unroll 4
    for (int e = 0; e < EMB; ++e) {
        float xe = __ldg(er + e);
        float2 wv = *(const float2*)(Wx + e * UNITS + u);
        acc.x = fmaf(xe, wv.x, acc.x);
        acc.y = fmaf(xe, wv.y, acc.y);
    }
    *(float2*)(g_etable + row * UNITS + u) = acc;
}

// ===== kernel 2: k-split, warp-private h, ONE barrier/step, SMEM-routed state =====
__global__ __launch_bounds__(NTHREADS, 8)
void rnn_scan(const int* __restrict__ tokens,
              const float* __restrict__ Wh,
              const float* __restrict__ Wfc,
              const float* __restrict__ bfc,
              float* __restrict__ out)
{
    __shared__ float  h_s[2][RPB][UNITS];        // per-warp private h copies, 4608 B
    __shared__ float2 part_s[2][2][RPB][32];     // [buf][writer][row][lane], 9216 B
    __shared__ float  xp_s[2][RPB][UNITS];       // [buf][row][unit], 4608 B
    __shared__ int    tok_s[SEQ][RPB];           // 2880 B (pre-scaled offsets)

    const int tid  = threadIdx.x;
    const int w    = tid >> 5;                   // warp: k-half owner
    const int l    = tid & 31;
    const int u0   = 2 * l;                      // units owned: u0, u0+1
    const int row0 = blockIdx.x * RPB;

    // ---- stage tokens (transposed [t][r]), clamped + pre-scaled ----
    for (int i = tid; i < SEQ * RPB; i += NTHREADS) {
        int t = i / RPB, r = i - t * RPB;
        int gr = row0 + r;
        if (gr >= NB) gr = NB - 1;               // clamp ragged tail
        tok_s[t][r] = tokens[gr * SEQ + t] * UNITS;
    }
    // ---- zero both private h copies ----
    for (int i = tid; i < 2 * RPB * UNITS; i += NTHREADS)
        ((float*)h_s)[i] = 0.0f;

    // ---- this warp's k-half of Wh, k-paired, into 32 u64 registers ----
    u64 wu0[KP], wu1[KP];
    #pragma unroll
    for (int k2 = 0; k2 < KP; ++k2) {
        int kp = w * KP + k2;
        float2 a = *(const float2*)(Wh + (2 * kp)     * UNITS + u0);
        float2 b = *(const float2*)(Wh + (2 * kp + 1) * UNITS + u0);
        wu0[k2] = packf2(a.x, b.x);
        wu1[k2] = packf2(a.y, b.y);
    }
    __syncthreads();

    // xp staging rows: w0 -> rows 0..4 (5), w1 -> rows 5..8 (4)
    const int xb  = w * 5;                       // first staged row
    const int nxp = 5 - w;                       // 5 or 4 rows

    for (int t = 0; t < SEQ; ++t) {
        const int buf = t & 1;

        // ---- issue xp(t) gathers early: latency hidden by compute phase ----
        u64 xpv[5];
        #pragma unroll
        for (int i = 0; i < 5; ++i)
            if (i < nxp)
                xpv[i] = *(const u64*)(g_etable + tok_s[t][xb + i] + u0);

        // ---- partial h @ Wh over this warp's k-half (reads OWN h copy) ----
        u64 a0[RPB], a1[RPB];
        #pragma unroll
        for (int r = 0; r < RPB; ++r) {              // j = 0: init via MUL2
            ulonglong2 hv = *(const ulonglong2*)(&h_s[w][r][w * 32]);  // broadcast
            a0[r] = mul2(hv.x, wu0[0]);
            a1[r] = mul2(hv.x, wu1[0]);
            fma2(a0[r], hv.y, wu0[1]);
            fma2(a1[r], hv.y, wu1[1]);
        }
        #pragma unroll
        for (int j = 1; j < 8; ++j) {                // remaining 7 j-groups
            #pragma unroll
            for (int r = 0; r < RPB; ++r) {
                ulonglong2 hv = *(const ulonglong2*)(&h_s[w][r][w * 32 + 4 * j]);
                fma2(a0[r], hv.x, wu0[2 * j]);
                fma2(a1[r], hv.x, wu1[2 * j]);
                fma2(a0[r], hv.y, wu0[2 * j + 1]);
                fma2(a1[r], hv.y, wu1[2 * j + 1]);
            }
        }

        // ---- publish partials for ALL rows (a0/a1 die here) ----
        #pragma unroll
        for (int r = 0; r < RPB; ++r)
            part_s[buf][w][r][l] = make_float2(foldf(a0[r]), foldf(a1[r]));
        // ---- publish xp(t) for this warp's staged rows ----
        #pragma unroll
        for (int i = 0; i < 5; ++i)
            if (i < nxp)
                *(u64*)(&xp_s[buf][xb + i][u0]) = xpv[i];

        __syncthreads();    // single barrier: partials + xp visible

        // ---- reduce ALL rows (duplicated across warps), write OWN h copy ----
        #pragma unroll
        for (int r = 0; r < RPB; ++r) {
            float2 pa = part_s[buf][0][r][l];
            float2 pb = part_s[buf][1][r][l];
            u64 xv = *(const u64*)(&xp_s[buf][r][u0]);
            float x0, x1;
            asm("mov.b64 {%0, %1}, %2;" : "=f"(x0), "=f"(x1) : "l"(xv));
            float v0 = pa.x + pb.x + x0;
            float v1 = pa.y + pb.y + x1;
            *(u64*)(&h_s[w][r][u0]) = packf2(tanhx(v0), tanhx(v1));
        }
        // no second barrier: next compute reads only this warp's own h copy;
        // part_s/xp_s WAR across steps covered by parity buffers + next BAR.
    }

    // ---- final FC + sigmoid: warp 0, lanes 0..8 (reads warp-0's h copy) ----
    __syncwarp();
    if (w == 0 && l < RPB && row0 + l < NB) {
        const float* hf = h_s[0][l];
        float dot = 0.0f;
        #pragma unroll 8
        for (int v = 0; v < UNITS; ++v) dot += hf[v] * __ldg(Wfc + v);
        float logit = dot + __ldg(bfc);
        out[row0 + l] = 1.0f / (1.0f + __expf(-logit));
    }
}

extern "C" void kernel_launch(void* const* d_in, const int* in_sizes, int n_in,
                              void* d_out, int out_size) {
    const int*   tokens = (const int*)  d_in[0];
    const float* emb    = (const float*)d_in[1];
    const float* Wx     = (const float*)d_in[2];
    const float* Wh     = (const float*)d_in[3];
    const float* b      = (const float*)d_in[4];
    const float* Wfc    = (const float*)d_in[5];
    const float* bfc    = (const float*)d_in[6];
    float* out          = (float*)d_out;

    build_etable<<<VOCAB / 8, 256>>>(emb, Wx, b);
    rnn_scan<<<GRID, NTHREADS>>>(tokens, Wh, Wfc, bfc, out);
}

// round 16
// speedup vs baseline: 1.1995x; 1.1267x over previous
#include <cuda_runtime.h>

#define NB        10000
#define VOCAB     10000
#define SEQ       80
#define EMB       100
#define UNITS     64
#define RPB       12          // rows per block -> grid = 834 (single wave @ occ 6)
#define GRID      ((NB + RPB - 1) / RPB)   // 834
#define NTHREADS  128         // 4 warps; warp w owns k-quarter [16w, 16w+16)
#define KP        8           // k-pairs per warp
#define RRED      3           // rows reduced per warp (4*3 = 12)

// precomputed ETable[v][u] = emb[v] @ Wx[:,u] + b[u]
__device__ float g_etable[VOCAB * UNITS];

typedef unsigned long long u64;

__device__ __forceinline__ void fma2(u64& d, u64 a, u64 b) {
    asm("fma.rn.f32x2 %0, %1, %2, %0;" : "+l"(d) : "l"(a), "l"(b));
}
__device__ __forceinline__ u64 mul2(u64 a, u64 b) {
    u64 r; asm("mul.rn.f32x2 %0, %1, %2;" : "=l"(r) : "l"(a), "l"(b)); return r;
}
__device__ __forceinline__ u64 packf2(float lo, float hi) {
    u64 r; asm("mov.b64 %0, {%1, %2};" : "=l"(r) : "f"(lo), "f"(hi)); return r;
}
__device__ __forceinline__ float foldf(u64 v) {
    float lo, hi;
    asm("mov.b64 {%0, %1}, %2;" : "=f"(lo), "=f"(hi) : "l"(v));
    return lo + hi;
}
__device__ __forceinline__ float tanhx(float x) {
    float r; asm("tanh.approx.f32 %0, %1;" : "=f"(r) : "f"(x)); return r;
}

// ============ kernel 1: ETable = emb @ Wx + b (one-shot, 64M MACs) ============
__global__ __launch_bounds__(256)
void build_etable(const float* __restrict__ emb,
                  const float* __restrict__ Wx,
                  const float* __restrict__ bias)
{
    const int w = threadIdx.x >> 5, l = threadIdx.x & 31;
    const int row = blockIdx.x * 8 + w;      // 1250 * 8 = 10000 exact
    const int u = l * 2;
    float2 acc = make_float2(bias[u], bias[u + 1]);
    const float* er = emb + row * EMB;
    #pragma unroll 4
    for (int e = 0; e < EMB; ++e) {
        float xe = __ldg(er + e);
        float2 wv = *(const float2*)(Wx + e * UNITS + u);
        acc.x = fmaf(xe, wv.x, acc.x);
        acc.y = fmaf(xe, wv.y, acc.y);
    }
    *(float2*)(g_etable + row * UNITS + u) = acc;
}

// ===== kernel 2: 4-warp k-quarter split, row-blocked acc, occ 6 =====
__global__ __launch_bounds__(NTHREADS, 6)
void rnn_scan(const int* __restrict__ tokens,
              const float* __restrict__ Wh,
              const float* __restrict__ Wfc,
              const float* __restrict__ bfc,
              float* __restrict__ out)
{
    __shared__ float  h_s[RPB][UNITS];          // 3072 B
    __shared__ float2 part_s[4][RPB][32];       // 12288 B: [writer warp][row][lane]
    __shared__ int    tok_s[SEQ][RPB];          // 3840 B (pre-scaled offsets)

    const int tid  = threadIdx.x;
    const int w    = tid >> 5;                  // warp: k-quarter owner
    const int l    = tid & 31;
    const int u0   = 2 * l;                     // units owned: u0, u0+1
    const int kw   = 16 * w;                    // first h index of this k-quarter
    const int row0 = blockIdx.x * RPB;

    // ---- stage tokens (transposed [t][r]), clamped + pre-scaled ----
    for (int i = tid; i < SEQ * RPB; i += NTHREADS) {
        int t = i / RPB, r = i - t * RPB;
        int gr = row0 + r;
        if (gr >= NB) gr = NB - 1;              // clamp ragged tail
        tok_s[t][r] = tokens[gr * SEQ + t] * UNITS;
    }
    // ---- zero h ----
    for (int i = tid; i < RPB * UNITS; i += NTHREADS)
        ((float*)h_s)[i] = 0.0f;

    // ---- this warp's k-quarter of Wh, k-paired, into 16 u64 registers ----
    u64 wu0[KP], wu1[KP];
    #pragma unroll
    for (int k2 = 0; k2 < KP; ++k2) {
        int kp = w * KP + k2;
        float2 a = *(const float2*)(Wh + (2 * kp)     * UNITS + u0);
        float2 b = *(const float2*)(Wh + (2 * kp + 1) * UNITS + u0);
        wu0[k2] = packf2(a.x, b.x);
        wu1[k2] = packf2(a.y, b.y);
    }
    __syncthreads();

    // ---- xp(0) for this warp's reduce rows (3w .. 3w+2) ----
    const int rown = RRED * w;
    float2 xc[RRED];
    #pragma unroll
    for (int i = 0; i < RRED; ++i)
        xc[i] = *(const float2*)(g_etable + tok_s[0][rown + i] + u0);

    for (int t = 0; t < SEQ; ++t) {
        // ---- partial h @ Wh over this warp's k-quarter, 3 rows at a time ----
        #pragma unroll
        for (int g = 0; g < 4; ++g) {
            const int rb = g * 3;
            u64 a0[3], a1[3];
            #pragma unroll
            for (int i = 0; i < 3; ++i) {            // jj = 0: init via MUL2
                ulonglong2 hv = *(const ulonglong2*)(&h_s[rb + i][kw]); // bcast
                a0[i] = mul2(hv.x, wu0[0]);
                a1[i] = mul2(hv.x, wu1[0]);
                fma2(a0[i], hv.y, wu0[1]);
                fma2(a1[i], hv.y, wu1[1]);
            }
            #pragma unroll
            for (int jj = 1; jj < 4; ++jj) {         // remaining 3 j-groups
                #pragma unroll
                for (int i = 0; i < 3; ++i) {
                    ulonglong2 hv = *(const ulonglong2*)(&h_s[rb + i][kw + 4 * jj]);
                    fma2(a0[i], hv.x, wu0[2 * jj]);
                    fma2(a1[i], hv.x, wu1[2 * jj]);
                    fma2(a0[i], hv.y, wu0[2 * jj + 1]);
                    fma2(a1[i], hv.y, wu1[2 * jj + 1]);
                }
            }
            // fold + publish this row group (acc dies here)
            #pragma unroll
            for (int i = 0; i < 3; ++i)
                part_s[w][rb + i][l] = make_float2(foldf(a0[i]), foldf(a1[i]));
        }
        __syncthreads();    // all partials visible; all h reads of this step done

        // ---- reduce + tanh + write new h: warp w -> rows 3w .. 3w+2 ----
        #pragma unroll
        for (int i = 0; i < RRED; ++i) {
            int r = rown + i;
            float2 p0 = part_s[0][r][l];
            float2 p1 = part_s[1][r][l];
            float2 p2 = part_s[2][r][l];
            float2 p3 = part_s[3][r][l];
            float v0 = (p0.x + p1.x) + (p2.x + p3.x) + xc[i].x;
            float v1 = (p0.y + p1.y) + (p2.y + p3.y) + xc[i].y;
            *(u64*)(&h_s[r][u0]) = packf2(tanhx(v0), tanhx(v1));
        }

        // ---- reload xc for t+1 (covered by barrier + next compute phase) ----
        const int tn = (t + 1 < SEQ) ? (t + 1) : (SEQ - 1);
        #pragma unroll
        for (int i = 0; i < RRED; ++i)
            xc[i] = *(const float2*)(g_etable + tok_s[tn][rown + i] + u0);

        __syncthreads();    // new h visible to all warps
    }

    // ---- final FC + sigmoid: threads 0..11 each handle one row ----
    if (tid < RPB && row0 + tid < NB) {
        const float* hf = h_s[tid];
        float dot = 0.0f;
        #pragma unroll 8
        for (int v = 0; v < UNITS; ++v) dot += hf[v] * __ldg(Wfc + v);
        float logit = dot + __ldg(bfc);
        out[row0 + tid] = 1.0f / (1.0f + __expf(-logit));
    }
}

extern "C" void kernel_launch(void* const* d_in, const int* in_sizes, int n_in,
                              void* d_out, int out_size) {
    const int*   tokens = (const int*)  d_in[0];
    const float* emb    = (const float*)d_in[1];
    const float* Wx     = (const float*)d_in[2];
    const float* Wh     = (const float*)d_in[3];
    const float* b      = (const float*)d_in[4];
    const float* Wfc    = (const float*)d_in[5];
    const float* bfc    = (const float*)d_in[6];
    float* out          = (float*)d_out;

    build_etable<<<VOCAB / 8, 256>>>(emb, Wx, b);
    rnn_scan<<<GRID, NTHREADS>>>(tokens, Wh, Wfc, bfc, out);
}

// round 17
// speedup vs baseline: 1.2126x; 1.0108x over previous
#include <cuda_runtime.h>

#define NB        10000
#define VOCAB     10000
#define SEQ       80
#define EMB       100
#define UNITS     64
#define RPB       10          // rows per block -> grid = 1000 exact (single wave @ occ 7)
#define GRID      (NB / RPB)  // 1000
#define NTHREADS  128         // 4 warps; warp w owns k-quarter [16w, 16w+16)
#define KP        8           // k-pairs per warp
#define RRED      3           // rows reduced per warp (w3 overlaps rows 7-8: benign)

// precomputed ETable[v][u] = emb[v] @ Wx[:,u] + b[u]
__device__ float g_etable[VOCAB * UNITS];

typedef unsigned long long u64;

__device__ __forceinline__ void fma2(u64& d, u64 a, u64 b) {
    asm("fma.rn.f32x2 %0, %1, %2, %0;" : "+l"(d) : "l"(a), "l"(b));
}
__device__ __forceinline__ u64 mul2(u64 a, u64 b) {
    u64 r; asm("mul.rn.f32x2 %0, %1, %2;" : "=l"(r) : "l"(a), "l"(b)); return r;
}
__device__ __forceinline__ u64 packf2(float lo, float hi) {
    u64 r; asm("mov.b64 %0, {%1, %2};" : "=l"(r) : "f"(lo), "f"(hi)); return r;
}
__device__ __forceinline__ float foldf(u64 v) {
    float lo, hi;
    asm("mov.b64 {%0, %1}, %2;" : "=f"(lo), "=f"(hi) : "l"(v));
    return lo + hi;
}
__device__ __forceinline__ float tanhx(float x) {
    float r; asm("tanh.approx.f32 %0, %1;" : "=f"(r) : "f"(x)); return r;
}

// ============ kernel 1: ETable = emb @ Wx + b (one-shot, 64M MACs) ============
__global__ __launch_bounds__(256)
void build_etable(const float* __restrict__ emb,
                  const float* __restrict__ Wx,
                  const float* __restrict__ bias)
{
    const int w = threadIdx.x >> 5, l = threadIdx.x & 31;
    const int row = blockIdx.x * 8 + w;      // 1250 * 8 = 10000 exact
    const int u = l * 2;
    // two independent chains to halve the serial FMA dependency
    float2 accA = make_float2(bias[u], bias[u + 1]);
    float2 accB = make_float2(0.0f, 0.0f);
    const float* er = emb + row * EMB;
    #pragma unroll 5
    for (int e = 0; e < EMB; e += 2) {
        float xe0 = __ldg(er + e);
        float xe1 = __ldg(er + e + 1);
        float2 w0 = *(const float2*)(Wx + e * UNITS + u);
        float2 w1 = *(const float2*)(Wx + (e + 1) * UNITS + u);
        accA.x = fmaf(xe0, w0.x, accA.x);
        accA.y = fmaf(xe0, w0.y, accA.y);
        accB.x = fmaf(xe1, w1.x, accB.x);
        accB.y = fmaf(xe1, w1.y, accB.y);
    }
    *(float2*)(g_etable + row * UNITS + u) =
        make_float2(accA.x + accB.x, accA.y + accB.y);
}

// ===== kernel 2: 4-warp k-quarter split, RPB=10, occ 7, single wave =====
__global__ __launch_bounds__(NTHREADS, 7)
void rnn_scan(const int* __restrict__ tokens,
              const float* __restrict__ Wh,
              const float* __restrict__ Wfc,
              const float* __restrict__ bfc,
              float* __restrict__ out)
{
    __shared__ float  h_s[RPB][UNITS];          // 2560 B
    __shared__ float2 part_s[4][RPB][32];       // 10240 B: [writer warp][row][lane]
    __shared__ int    tok_s[SEQ][RPB];          // 3200 B (pre-scaled offsets)

    const int tid  = threadIdx.x;
    const int w    = tid >> 5;                  // warp: k-quarter owner
    const int l    = tid & 31;
    const int u0   = 2 * l;                     // units owned: u0, u0+1
    const int kw   = 16 * w;                    // first h index of this k-quarter
    const int row0 = blockIdx.x * RPB;

    // ---- stage tokens (transposed [t][r]), pre-scaled (exact tiling) ----
    for (int i = tid; i < SEQ * RPB; i += NTHREADS) {
        int t = i / RPB, r = i - t * RPB;
        tok_s[t][r] = tokens[(row0 + r) * SEQ + t] * UNITS;
    }
    // ---- zero h ----
    for (int i = tid; i < RPB * UNITS; i += NTHREADS)
        ((float*)h_s)[i] = 0.0f;

    // ---- this warp's k-quarter of Wh, k-paired, into 16 u64 registers ----
    u64 wu0[KP], wu1[KP];
    #pragma unroll
    for (int k2 = 0; k2 < KP; ++k2) {
        int kp = w * KP + k2;
        float2 a = *(const float2*)(Wh + (2 * kp)     * UNITS + u0);
        float2 b = *(const float2*)(Wh + (2 * kp + 1) * UNITS + u0);
        wu0[k2] = packf2(a.x, b.x);
        wu1[k2] = packf2(a.y, b.y);
    }
    __syncthreads();

    // reduce rows: w0 -> 0..2, w1 -> 3..5, w2 -> 6..8, w3 -> 7..9
    // (rows 7,8 dual-reduced with identical values: benign)
    const int rown = (w < 3) ? (3 * w) : 7;

    // ---- xp(0) for this warp's reduce rows ----
    float2 xc[RRED];
    #pragma unroll
    for (int i = 0; i < RRED; ++i)
        xc[i] = *(const float2*)(g_etable + tok_s[0][rown + i] + u0);

    for (int t = 0; t < SEQ; ++t) {
        // ---- partial h @ Wh over this warp's k-quarter, 2 rows at a time ----
        #pragma unroll
        for (int g = 0; g < 5; ++g) {
            const int rb = g * 2;
            u64 a0[2], a1[2];
            #pragma unroll
            for (int i = 0; i < 2; ++i) {            // jj = 0: init via MUL2
                ulonglong2 hv = *(const ulonglong2*)(&h_s[rb + i][kw]); // bcast
                a0[i] = mul2(hv.x, wu0[0]);
                a1[i] = mul2(hv.x, wu1[0]);
                fma2(a0[i], hv.y, wu0[1]);
                fma2(a1[i], hv.y, wu1[1]);
            }
            #pragma unroll
            for (int jj = 1; jj < 4; ++jj) {         // remaining 3 j-groups
                #pragma unroll
                for (int i = 0; i < 2; ++i) {
                    ulonglong2 hv = *(const ulonglong2*)(&h_s[rb + i][kw + 4 * jj]);
                    fma2(a0[i], hv.x, wu0[2 * jj]);
                    fma2(a1[i], hv.x, wu1[2 * jj]);
                    fma2(a0[i], hv.y, wu0[2 * jj + 1]);
                    fma2(a1[i], hv.y, wu1[2 * jj + 1]);
                }
            }
            // fold + publish this row group (acc dies here)
            #pragma unroll
            for (int i = 0; i < 2; ++i)
                part_s[w][rb + i][l] = make_float2(foldf(a0[i]), foldf(a1[i]));
        }
        __syncthreads();    // all partials visible; all h reads of this step done

        // ---- reduce + tanh + write new h for this warp's rows ----
        #pragma unroll
        for (int i = 0; i < RRED; ++i) {
            int r = rown + i;
            float2 p0 = part_s[0][r][l];
            float2 p1 = part_s[1][r][l];
            float2 p2 = part_s[2][r][l];
            float2 p3 = part_s[3][r][l];
            float v0 = (p0.x + p1.x) + (p2.x + p3.x) + xc[i].x;
            float v1 = (p0.y + p1.y) + (p2.y + p3.y) + xc[i].y;
            *(u64*)(&h_s[r][u0]) = packf2(tanhx(v0), tanhx(v1));
        }

        // ---- reload xc for t+1 (covered by barrier + next compute phase) ----
        const int tn = (t + 1 < SEQ) ? (t + 1) : (SEQ - 1);
        #pragma unroll
        for (int i = 0; i < RRED; ++i)
            xc[i] = *(const float2*)(g_etable + tok_s[tn][rown + i] + u0);

        __syncthreads();    // new h visible to all warps
    }

    // ---- final FC + sigmoid: threads 0..9 each handle one row ----
    if (tid < RPB) {
        const float* hf = h_s[tid];
        float dot = 0.0f;
        #pragma unroll 8
        for (int v = 0; v < UNITS; ++v) dot += hf[v] * __ldg(Wfc + v);
        float logit = dot + __ldg(bfc);
        out[row0 + tid] = 1.0f / (1.0f + __expf(-logit));
    }
}

extern "C" void kernel_launch(void* const* d_in, const int* in_sizes, int n_in,
                              void* d_out, int out_size) {
    const int*   tokens = (const int*)  d_in[0];
    const float* emb    = (const float*)d_in[1];
    const float* Wx     = (const float*)d_in[2];
    const float* Wh     = (const float*)d_in[3];
    const float* b      = (const float*)d_in[4];
    const float* Wfc    = (const float*)d_in[5];
    const float* bfc    = (const float*)d_in[6];
    float* out          = (float*)d_out;

    build_etable<<<VOCAB / 8, 256>>>(emb, Wx, b);
    rnn_scan<<<GRID, NTHREADS>>>(tokens, Wh, Wfc, bfc, out);
}